// round 16
// baseline (speedup 1.0000x reference)
#include <cuda_runtime.h>
#include <cuda_bf16.h>

// SSIM loss — windowless vertical: the value leaving the 11-row box is
// re-loaded from L2 and recomputed instead of being held in a register
// sliding window (-22 regs). Freed registers spent on occupancy:
// launch_bounds(256,6), 768 blocks (24 bands x 2 halves x 16 images).

#define IMG    512
#define CROP   492
#define SHAVE  10
#define PLANE  (IMG * IMG)

#define NBANDS 24
#define RROWS  21
#define GROWS  7
#define NBATCH (RROWS / GROWS)   // 3
#define HALF   246               // output columns per block
#define WID4   272               // smem row capacity
#define NT     256
#define NBLOCKS (NBANDS * 2 * 16)   // 768

#define SWZ4(i) ((i) ^ (((i) >> 3) & 7))
#define Q4(g, i) ((g) * WID4 + SWZ4(i))

#define SMEM_BYTES (GROWS * WID4 * 16)   // 30464

__device__ double   g_part[NBLOCKS];
__device__ unsigned g_count = 0;

__device__ __forceinline__ float yval(float c0, float c1, float c2)
{
    const float W0 = 65.738f  / (256.0f * 255.0f);
    const float W1 = 129.057f / (256.0f * 255.0f);
    const float W2 = 25.064f  / (256.0f * 255.0f);
    return fmaf(c0, W0, fmaf(c1, W1, c2 * W2));
}

// one vertical-window insert without a register window:
// new row at (ry, off); old row (leaving the 11-tap box) re-loaded at ry-11.
template<bool USE_OLD, bool LOW_CHECK>
__device__ __forceinline__ void insert(
    const float* __restrict__ A, const float* __restrict__ B,
    int off, int ry, bool col_ok,
    float& Sp, float& Sm, float& Spp, float& Smm)
{
    float p = 0.f, m = 0.f;
    bool nv = col_ok && (ry < CROP) && (!LOW_CHECK || ry >= 0);
    if (nv) {
        float a = yval(A[off], A[off + PLANE], A[off + 2*PLANE]);
        float b = yval(B[off], B[off + PLANE], B[off + 2*PLANE]);
        p = a + b; m = a - b;
    }
    float po = 0.f, mo = 0.f;
    if (USE_OLD) {
        int ryo  = ry - 11;
        int offo = off - 11 * IMG;
        if (col_ok && ryo >= 0 && ryo < CROP) {
            float ao = yval(A[offo], A[offo + PLANE], A[offo + 2*PLANE]);
            float bo = yval(B[offo], B[offo + PLANE], B[offo + 2*PLANE]);
            po = ao + bo; mo = ao - bo;
        }
    }
    float dp = p - po, dm = m - mo;
    Sp += dp;
    Sm += dm;
    Spp = fmaf(dp, p + po, Spp);    // p^2 - po^2
    Smm = fmaf(dm, m + mo, Smm);
}

__global__ __launch_bounds__(NT, 6)
void ssim_band_kernel(const float* __restrict__ sr, const float* __restrict__ hr,
                      float* __restrict__ out, const void* __restrict__ bs_ptr)
{
    extern __shared__ char smem_raw[];
    float4* cs4 = (float4*)smem_raw;      // [GROWS][WID4] packed (Sp,Sm,Spp,Smm)

    __shared__ float  redf[NT / 32];
    __shared__ double redd[NT / 32];
    __shared__ int    s_last;

    const int t    = threadIdx.x;
    const int bx   = blockIdx.x;          // 0..47
    const int band = bx >> 1;             // 0..23
    const int half = bx & 1;              // 0..1
    const int n    = blockIdx.y;
    const int oy0  = band * RROWS;
    const int base = half * HALF;         // global x of local output 0

    const float* A = sr + (size_t)n * 3 * PLANE;
    const float* B = hr + (size_t)n * 3 * PLANE;

    // zero cs plane once
    for (int i = t; i < GROWS * WID4; i += NT)
        cs4[i] = make_float4(0.f, 0.f, 0.f, 0.f);

    float Sp = 0.f, Sm = 0.f, Spp = 0.f, Smm = 0.f;

    const int  gx     = base + t - 5;               // global Y-image column
    const bool col_ok = (gx >= 0) && (gx < CROP);
    int ry  = oy0 - 5;
    int off = (ry + SHAVE) * IMG + (gx + SHAVE);

    // ---- warm-up: 10 row inserts (insert index r=0..9: never an old row) ----
    #pragma unroll
    for (int i = 0; i < 10; i++) {
        insert<false, true>(A, B, off, ry, col_ok, Sp, Sm, Spp, Smm);
        ry++; off += IMG;
    }
    __syncthreads();

    const float inv121 = 1.0f / 121.0f;
    const float C1 = 6.5025f;
    const float C2 = 58.5225f;

    float acc = 0.0f;

    #pragma unroll
    for (int jb = 0; jb < NBATCH; jb++) {
        // ---- vertical: insert GROWS rows, emit packed float4 ----
        #pragma unroll
        for (int g = 0; g < GROWS; g++) {
            // global insert index r = 10 + jb*GROWS + g; old row exists iff r >= 11
            if (jb == 0 && g == 0)
                insert<false, false>(A, B, off, ry, col_ok, Sp, Sm, Spp, Smm);
            else
                insert<true, false>(A, B, off, ry, col_ok, Sp, Sm, Spp, Smm);
            ry++; off += IMG;
            cs4[Q4(g, t)] = make_float4(Sp, Sm, Spp, Smm);
        }
        __syncthreads();

        // ---- horizontal: 31 runs x 7 rows, runs of 8 (stride-8 swizzle) ----
        if (t < 217) {
            int row = t / 31;             // 0..6
            int run = t % 31;             // 0..30
            int x0  = run * 8;            // 0..240
            int gy  = oy0 + jb * GROWS + row;
            if (gy < CROP) {
                float HP = 0.f, HM = 0.f, HPP = 0.f, HMM = 0.f;
                #pragma unroll
                for (int d = 0; d < 11; d++) {
                    float4 q = cs4[Q4(row, x0 + d)];
                    HP += q.x; HM += q.y; HPP += q.z; HMM += q.w;
                }
                #pragma unroll
                for (int mm = 0; mm < 8; mm++) {
                    if (x0 + mm < HALF) {
                        float muP = HP * inv121;
                        float muM = HM * inv121;
                        float muP2 = muP * muP;
                        float muM2 = muM * muM;
                        float mu1mu2 = 0.25f * (muP2 - muM2);
                        float musq   = 0.5f  * (muP2 + muM2);
                        float sab    = 0.25f * (HPP - HMM);
                        float ssq    = 0.5f  * (HPP + HMM);
                        float sigma12 = fmaf(sab, inv121, -mu1mu2);
                        float sigsum  = fmaf(ssq, inv121, -musq);
                        float num = fmaf(2.0f, mu1mu2, C1) * fmaf(2.0f, sigma12, C2);
                        float den = (musq + C1) * (sigsum + C2);
                        acc += 1.0f - __fdividef(num, den);
                    }
                    if (mm < 7) {
                        float4 qo = cs4[Q4(row, x0 + mm)];
                        float4 qn = cs4[Q4(row, x0 + mm + 11)];
                        HP  += qn.x - qo.x;
                        HM  += qn.y - qo.y;
                        HPP += qn.z - qo.z;
                        HMM += qn.w - qo.w;
                    }
                }
            }
        }
        __syncthreads();
    }

    // ---- block reduction -> per-block partial ----
    #pragma unroll
    for (int o = 16; o > 0; o >>= 1)
        acc += __shfl_down_sync(0xffffffffu, acc, o);
    int lane = t & 31, warp = t >> 5;
    if (lane == 0) redf[warp] = acc;
    __syncthreads();
    if (warp == 0) {
        float v = (lane < NT / 32) ? redf[lane] : 0.0f;
        #pragma unroll
        for (int o = 16; o > 0; o >>= 1)
            v += __shfl_down_sync(0xffffffffu, v, o);
        if (lane == 0)
            g_part[(n * NBANDS + band) * 2 + half] = (double)v;
    }

    // ---- last block performs the global reduction ----
    if (t == 0) {
        __threadfence();
        unsigned old = atomicAdd(&g_count, 1u);
        s_last = (old == NBLOCKS - 1) ? 1 : 0;
    }
    __syncthreads();
    if (s_last) {
        double v = 0.0;
        for (int i = t; i < NBLOCKS; i += NT) v += g_part[i];
        #pragma unroll
        for (int o = 16; o > 0; o >>= 1)
            v += __shfl_down_sync(0xffffffffu, v, o);
        if (lane == 0) redd[warp] = v;
        __syncthreads();
        if (warp == 0) {
            double s = (lane < NT / 32) ? redd[lane] : 0.0;
            #pragma unroll
            for (int o = 16; o > 0; o >>= 1)
                s += __shfl_down_sync(0xffffffffu, s, o);
            if (lane == 0) {
                float divisor = 16.0f;
                if (bs_ptr) {
                    int vi = *(const int*)bs_ptr;
                    if (vi > 0 && vi < 100000000) divisor = (float)vi;
                    else {
                        float vf = *(const float*)bs_ptr;
                        if (vf > 0.0f && vf < 1.0e8f) divisor = vf;
                    }
                }
                out[0]  = (float)(s / (double)divisor);
                g_count = 0;   // reset for next graph replay
            }
        }
    }
}

extern "C" void kernel_launch(void* const* d_in, const int* in_sizes, int n_in,
                              void* d_out, int out_size)
{
    const float* sr = (const float*)d_in[0];
    const float* hr = (const float*)d_in[1];
    const void* bs  = (n_in >= 3) ? d_in[2] : nullptr;
    float* out = (float*)d_out;

    cudaFuncSetAttribute(ssim_band_kernel,
                         cudaFuncAttributeMaxDynamicSharedMemorySize, SMEM_BYTES);

    dim3 grid(NBANDS * 2, 16);
    ssim_band_kernel<<<grid, NT, SMEM_BYTES>>>(sr, hr, out, bs);
}

// round 17
// speedup vs baseline: 1.5146x; 1.5146x over previous
#include <cuda_runtime.h>
#include <cuda_bf16.h>

// SSIM loss — R15 base (27.1us) + f32x2-packed accumulation in the
// HORIZONTAL phase only. Vertical keeps scalar math (its single serial
// accumulator chain must not be fused — R9 lesson). Horizontal tap/slide
// adds go 4 scalar chains -> 2 packed chains: half the FADD issue count in
// a phase with abundant warp/output parallelism.

#define IMG    512
#define CROP   492
#define SHAVE  10
#define PLANE  (IMG * IMG)

#define NBANDS 18
#define RROWS  28
#define GROWS  7
#define NBATCH (RROWS / GROWS)   // 4
#define HALF   246               // output columns per block
#define WID4   272               // smem row capacity
#define NT     256
#define NBLOCKS (NBANDS * 2 * 16)   // 576

#define SWZ4(i) ((i) ^ (((i) >> 3) & 7))
#define Q4(g, i) ((g) * WID4 + SWZ4(i))

#define SMEM_BYTES (GROWS * WID4 * 16)   // 30464

typedef unsigned long long u64;

#define UNPK2(lo, hi, s)  asm("mov.b64 {%0, %1}, %2;" : "=f"(lo), "=f"(hi) : "l"(s))
#define ADD2(d, a, b)     asm("add.rn.f32x2 %0, %1, %2;" : "=l"(d) : "l"(a), "l"(b))
#define FMA2(d, a, b, c)  asm("fma.rn.f32x2 %0, %1, %2, %3;" : "=l"(d) : "l"(a), "l"(b), "l"(c))

#define NEG1_BITS 0xBF800000BF800000ULL   // (-1.0f, -1.0f)

__device__ double   g_part[NBLOCKS];
__device__ unsigned g_count = 0;

__device__ __forceinline__ float yval(float c0, float c1, float c2)
{
    const float W0 = 65.738f  / (256.0f * 255.0f);
    const float W1 = 129.057f / (256.0f * 255.0f);
    const float W2 = 25.064f  / (256.0f * 255.0f);
    return fmaf(c0, W0, fmaf(c1, W1, c2 * W2));
}

__device__ __forceinline__ void push(
    float p, float m, float (&wp)[11], float (&wm)[11],
    float& Sp, float& Sm, float& Spp, float& Smm)
{
    float op = wp[0], om = wm[0];
    float dp = p - op, dm = m - om;
    float sp = p + op, sm = m + om;
    Sp  += dp;
    Sm  += dm;
    Spp = fmaf(dp, sp, Spp);            // p^2 - op^2
    Smm = fmaf(dm, sm, Smm);
    #pragma unroll
    for (int k = 0; k < 10; k++) { wp[k] = wp[k + 1]; wm[k] = wm[k + 1]; }
    wp[10] = p; wm[10] = m;
}

__global__ __launch_bounds__(NT, 4)
void ssim_band_kernel(const float* __restrict__ sr, const float* __restrict__ hr,
                      float* __restrict__ out, const void* __restrict__ bs_ptr)
{
    extern __shared__ char smem_raw[];
    float4*     cs4 = (float4*)smem_raw;      // [GROWS][WID4] (Sp,Sm,Spp,Smm)
    ulonglong2* cs8 = (ulonglong2*)smem_raw;  // same bytes: (Sp|Sm, Spp|Smm)

    __shared__ float  redf[NT / 32];
    __shared__ double redd[NT / 32];
    __shared__ int    s_last;

    const int t    = threadIdx.x;
    const int bx   = blockIdx.x;          // 0..35
    const int band = bx >> 1;             // 0..17
    const int half = bx & 1;              // 0..1
    const int n    = blockIdx.y;
    const int oy0  = band * RROWS;
    const int base = half * HALF;         // global x of local output 0

    const float* A = sr + (size_t)n * 3 * PLANE;
    const float* B = hr + (size_t)n * 3 * PLANE;

    const u64 NEG1 = NEG1_BITS;

    // zero cs plane once: halo/pad cells stay zero forever
    for (int i = t; i < GROWS * WID4; i += NT)
        cs4[i] = make_float4(0.f, 0.f, 0.f, 0.f);

    float wp[11], wm[11];
    #pragma unroll
    for (int k = 0; k < 11; k++) { wp[k] = 0.0f; wm[k] = 0.0f; }
    float Sp = 0.f, Sm = 0.f, Spp = 0.f, Smm = 0.f;

    const int  gx     = base + t - 5;               // global Y-image column
    const bool col_ok = (gx >= 0) && (gx < CROP);
    int ry  = oy0 - 5;
    int off = (ry + SHAVE) * IMG + (gx + SHAVE);

    // ---- warm-up: 10 row inserts ----
    #pragma unroll
    for (int i = 0; i < 10; i++) {
        bool v = col_ok && (ry >= 0) && (ry < CROP);
        float p = 0.f, m = 0.f;
        if (v) {
            float a = yval(A[off], A[off + PLANE], A[off + 2*PLANE]);
            float b = yval(B[off], B[off + PLANE], B[off + 2*PLANE]);
            p = a + b; m = a - b;
        }
        push(p, m, wp, wm, Sp, Sm, Spp, Smm);
        ry++; off += IMG;
    }
    __syncthreads();

    const float inv121 = 1.0f / 121.0f;
    const float C1 = 6.5025f;
    const float C2 = 58.5225f;

    float acc = 0.0f;

    #pragma unroll
    for (int jb = 0; jb < NBATCH; jb++) {
        // ---- vertical: insert GROWS rows, emit packed float4 ----
        #pragma unroll
        for (int g = 0; g < GROWS; g++) {
            bool v = col_ok && (ry < CROP);
            float p = 0.f, m = 0.f;
            if (v) {
                float a = yval(A[off], A[off + PLANE], A[off + 2*PLANE]);
                float b = yval(B[off], B[off + PLANE], B[off + 2*PLANE]);
                p = a + b; m = a - b;
            }
            push(p, m, wp, wm, Sp, Sm, Spp, Smm);
            ry++; off += IMG;
            cs4[Q4(g, t)] = make_float4(Sp, Sm, Spp, Smm);
        }
        __syncthreads();

        // ---- horizontal: 31 runs x 7 rows, runs of 8, packed f32x2 sums ----
        if (t < 217) {
            int row = t / 31;             // 0..6
            int run = t % 31;             // 0..30
            int x0  = run * 8;            // 0..240
            int gy  = oy0 + jb * GROWS + row;
            if (gy < CROP) {
                u64 H1 = 0ULL, H2 = 0ULL;
                #pragma unroll
                for (int d = 0; d < 11; d++) {
                    ulonglong2 q = cs8[Q4(row, x0 + d)];
                    ADD2(H1, H1, q.x);
                    ADD2(H2, H2, q.y);
                }
                #pragma unroll
                for (int mm = 0; mm < 8; mm++) {
                    if (x0 + mm < HALF) {
                        float HP, HM, HPP, HMM;
                        UNPK2(HP, HM, H1);
                        UNPK2(HPP, HMM, H2);
                        float muP = HP * inv121;
                        float muM = HM * inv121;
                        float muP2 = muP * muP;
                        float muM2 = muM * muM;
                        float mu1mu2 = 0.25f * (muP2 - muM2);
                        float musq   = 0.5f  * (muP2 + muM2);
                        float sab    = 0.25f * (HPP - HMM);
                        float ssq    = 0.5f  * (HPP + HMM);
                        float sigma12 = fmaf(sab, inv121, -mu1mu2);
                        float sigsum  = fmaf(ssq, inv121, -musq);
                        float num = fmaf(2.0f, mu1mu2, C1) * fmaf(2.0f, sigma12, C2);
                        float den = (musq + C1) * (sigsum + C2);
                        acc += 1.0f - __fdividef(num, den);
                    }
                    if (mm < 7) {
                        ulonglong2 qo = cs8[Q4(row, x0 + mm)];
                        ulonglong2 qn = cs8[Q4(row, x0 + mm + 11)];
                        ADD2(H1, H1, qn.x);
                        FMA2(H1, qo.x, NEG1, H1);
                        ADD2(H2, H2, qn.y);
                        FMA2(H2, qo.y, NEG1, H2);
                    }
                }
            }
        }
        __syncthreads();
    }

    // ---- block reduction -> per-block partial ----
    #pragma unroll
    for (int o = 16; o > 0; o >>= 1)
        acc += __shfl_down_sync(0xffffffffu, acc, o);
    int lane = t & 31, warp = t >> 5;
    if (lane == 0) redf[warp] = acc;
    __syncthreads();
    if (warp == 0) {
        float v = (lane < NT / 32) ? redf[lane] : 0.0f;
        #pragma unroll
        for (int o = 16; o > 0; o >>= 1)
            v += __shfl_down_sync(0xffffffffu, v, o);
        if (lane == 0)
            g_part[(n * NBANDS + band) * 2 + half] = (double)v;
    }

    // ---- last block performs the global reduction ----
    if (t == 0) {
        __threadfence();
        unsigned old = atomicAdd(&g_count, 1u);
        s_last = (old == NBLOCKS - 1) ? 1 : 0;
    }
    __syncthreads();
    if (s_last) {
        double v = 0.0;
        for (int i = t; i < NBLOCKS; i += NT) v += g_part[i];
        #pragma unroll
        for (int o = 16; o > 0; o >>= 1)
            v += __shfl_down_sync(0xffffffffu, v, o);
        if (lane == 0) redd[warp] = v;
        __syncthreads();
        if (warp == 0) {
            double s = (lane < NT / 32) ? redd[lane] : 0.0;
            #pragma unroll
            for (int o = 16; o > 0; o >>= 1)
                s += __shfl_down_sync(0xffffffffu, s, o);
            if (lane == 0) {
                float divisor = 16.0f;
                if (bs_ptr) {
                    int vi = *(const int*)bs_ptr;
                    if (vi > 0 && vi < 100000000) divisor = (float)vi;
                    else {
                        float vf = *(const float*)bs_ptr;
                        if (vf > 0.0f && vf < 1.0e8f) divisor = vf;
                    }
                }
                out[0]  = (float)(s / (double)divisor);
                g_count = 0;   // reset for next graph replay
            }
        }
    }
}

extern "C" void kernel_launch(void* const* d_in, const int* in_sizes, int n_in,
                              void* d_out, int out_size)
{
    const float* sr = (const float*)d_in[0];
    const float* hr = (const float*)d_in[1];
    const void* bs  = (n_in >= 3) ? d_in[2] : nullptr;
    float* out = (float*)d_out;

    cudaFuncSetAttribute(ssim_band_kernel,
                         cudaFuncAttributeMaxDynamicSharedMemorySize, SMEM_BYTES);

    dim3 grid(NBANDS * 2, 16);
    ssim_band_kernel<<<grid, NT, SMEM_BYTES>>>(sr, hr, out, bs);
}